// round 13
// baseline (speedup 1.0000x reference)
#include <cuda_runtime.h>
#include <cuda.h>
#include <cstdint>

// CorticalSheet fixed-degree SpMM:
//   out[n, b] = sum_k values[n, k] * x[indices[n, k], b] + bias[n]
// N = 1e6, K = 32, B = 8.
//
// R1..R11 established: any LDG-based kernel is pinned at ~139us by the L1tex
// wavefront service rate (32M gather wavefronts @ ~1.16 cyc/wf; scheduling,
// occupancy and cache-policy variants all neutral). This round routes the
// gathers through TMA tile::gather4 (SM -> LTS direct, no per-SM L1 wavefront
// per row): 512 gather4/CTA stage 64 neurons x 32 rows (32B each) into SMEM;
// compute consumes via conflict-free 128B LDS. New bound = LTS sector
// throughput ~ 1.35GB / 6300 B/cyc ~= 112us. L2 promotion OFF (promotion
// would fetch 128B per random 32B row = 4x LTS traffic).
//
// Tensormap encode via cudaGetDriverEntryPointByVersion (no -lcuda needed).
// Any host-side failure -> fallback to the proven R1 LDG kernel.
//
// (Identical to round-12 submission — never ran: GPU broker timeout.)

static constexpr int K_SYN = 32;
static constexpr int B_COL = 8;
static constexpr int ROW_BYTES = 32;                       // 8 floats
static constexpr int TILE_N = 64;                          // neurons per CTA
static constexpr int ROWS_PER_TILE = TILE_N * K_SYN;       // 2048
static constexpr int CHUNKS = ROWS_PER_TILE / 4;           // 512 gather4/CTA
static constexpr int THREADS = 256;

// SMEM layout (bytes)
static constexpr int SMEM_MBAR  = 0;                         // 8B mbarrier
static constexpr int SMEM_IDXT  = 128;                       // 2048 ints = 8192B
static constexpr int SMEM_ROWS  = SMEM_IDXT + ROWS_PER_TILE * 4;  // 8320 (128B aligned)
static constexpr int SMEM_TOTAL = SMEM_ROWS + CHUNKS * 128;  // 8320 + 65536 = 73856

// ---------------------------------------------------------------------------
// TMA gather kernel
// ---------------------------------------------------------------------------
__global__ __launch_bounds__(THREADS)
void cortical_tma_kernel(const __grid_constant__ CUtensorMap tmap,
                         const float* __restrict__ values,
                         const float* __restrict__ bias,
                         const int*   __restrict__ indices,
                         float* __restrict__ out) {
    extern __shared__ __align__(128) char smem[];
    uint32_t sb;
    asm("{ .reg .u64 t; cvta.to.shared.u64 t, %1; cvt.u32.u64 %0, t; }"
        : "=r"(sb) : "l"(smem));

    const int tid  = threadIdx.x;
    const long n0  = (long)blockIdx.x * TILE_N;

    if (tid == 0) {
        asm volatile("mbarrier.init.shared.b64 [%0], 1;"
                     :: "r"(sb + SMEM_MBAR) : "memory");
    }

    // ---- Phase 1: stage indices transposed: idxT[k*TILE_N + ln] ----
    {
        const int* idx_g = indices + n0 * K_SYN;
        const int4 A = *reinterpret_cast<const int4*>(idx_g + tid * 8);
        const int4 Bv = *reinterpret_cast<const int4*>(idx_g + tid * 8 + 4);
        int* idxT = reinterpret_cast<int*>(smem + SMEM_IDXT);
        const int vals[8] = {A.x, A.y, A.z, A.w, Bv.x, Bv.y, Bv.z, Bv.w};
        const int e0 = tid * 8;
        #pragma unroll
        for (int j = 0; j < 8; ++j) {
            const int e  = e0 + j;
            const int ln = e >> 5;       // local neuron
            const int k  = e & 31;       // synapse
            idxT[k * TILE_N + ln] = vals[j];
        }
    }
    __syncthreads();

    if (tid == 0) {
        asm volatile("mbarrier.arrive.expect_tx.shared.b64 _, [%0], %1;"
                     :: "r"(sb + SMEM_MBAR),
                        "r"((unsigned)(ROWS_PER_TILE * ROW_BYTES)) : "memory");
    }

    // ---- Phase 2: issue 512 gather4 (2 per thread) ----
    // Chunk c = k*16 + lgrp gathers rows (neurons 4*lgrp..4*lgrp+3, synapse k)
    // into SMEM_ROWS + c*128 (4 rows x 32B, packed).
    {
        const int* idxT = reinterpret_cast<const int*>(smem + SMEM_IDXT);
        #pragma unroll
        for (int cc = 0; cc < 2; ++cc) {
            const int c  = tid + cc * THREADS;
            const int k  = c >> 4;
            const int lg = c & 15;
            const int4 rows = *reinterpret_cast<const int4*>(idxT + k * TILE_N + lg * 4);
            const uint32_t dst = sb + SMEM_ROWS + c * 128;
            asm volatile(
                "cp.async.bulk.tensor.2d.shared::cta.global.tile::gather4"
                ".mbarrier::complete_tx::bytes"
                " [%0], [%1, {%2, %3, %4, %5, %6}], [%7];"
                :: "r"(dst), "l"(&tmap), "r"(0),
                   "r"(rows.x), "r"(rows.y), "r"(rows.z), "r"(rows.w),
                   "r"(sb + SMEM_MBAR) : "memory");
        }
    }

    // ---- Wait for all 64KB to land ----
    {
        const uint32_t mb = sb + SMEM_MBAR;
        uint32_t done = 0;
        while (!done) {
            asm volatile(
                "{ .reg .pred p;"
                "  mbarrier.try_wait.parity.acquire.cta.shared::cta.b64 p, [%1], 0, 0x989680;"
                "  selp.b32 %0, 1, 0, p; }"
                : "=r"(done) : "r"(mb) : "memory");
        }
    }

    // ---- Phase 3: compute. 8 warps x 4 neurons x 2 passes = 64 neurons ----
    const int lane  = tid & 31;
    const int warp  = tid >> 5;
    const int b     = lane & 7;
    const int gbase = lane & 24;
    const float* rows_s = reinterpret_cast<const float*>(smem + SMEM_ROWS);

    #pragma unroll
    for (int pass = 0; pass < 2; ++pass) {
        const int  ln = pass * 32 + warp * 4 + (lane >> 3);
        const long n  = n0 + ln;
        const int  lgrp = ln >> 2;     // chunk group of this neuron
        const int  li   = ln & 3;      // row slot within chunk

        const float4 val4 = __ldg(reinterpret_cast<const float4*>(
                                      values + (size_t)n * K_SYN + (size_t)b * 4));

        float a0 = 0.f, a1 = 0.f, a2 = 0.f, a3 = 0.f;
        #pragma unroll
        for (int k4 = 0; k4 < 8; ++k4) {
            const int src = gbase + k4;   // lane holding values k4*4..k4*4+3
            const float v0 = __shfl_sync(0xffffffffu, val4.x, src);
            const float v1 = __shfl_sync(0xffffffffu, val4.y, src);
            const float v2 = __shfl_sync(0xffffffffu, val4.z, src);
            const float v3 = __shfl_sync(0xffffffffu, val4.w, src);
            // float index of row (k, ln), col b: (k*16+lgrp)*32 + li*8 + b
            const float g0 = rows_s[((k4 * 4 + 0) * 16 + lgrp) * 32 + li * 8 + b];
            const float g1 = rows_s[((k4 * 4 + 1) * 16 + lgrp) * 32 + li * 8 + b];
            const float g2 = rows_s[((k4 * 4 + 2) * 16 + lgrp) * 32 + li * 8 + b];
            const float g3 = rows_s[((k4 * 4 + 3) * 16 + lgrp) * 32 + li * 8 + b];
            a0 = fmaf(v0, g0, a0);
            a1 = fmaf(v1, g1, a1);
            a2 = fmaf(v2, g2, a2);
            a3 = fmaf(v3, g3, a3);
        }
        out[(size_t)n * B_COL + b] = ((a0 + a1) + (a2 + a3)) + __ldg(bias + n);
    }
}

// ---------------------------------------------------------------------------
// Fallback: proven R1 LDG kernel (139.4us), with a start offset so it can
// also serve as a remainder kernel.
// ---------------------------------------------------------------------------
__global__ __launch_bounds__(256)
void cortical_spmm_kernel(const float* __restrict__ x,
                          const float* __restrict__ values,
                          const float* __restrict__ bias,
                          const int*   __restrict__ indices,
                          float* __restrict__ out,
                          int n_start, int N) {
    const int tid   = blockIdx.x * blockDim.x + threadIdx.x;
    const int warp  = tid >> 5;
    const int lane  = threadIdx.x & 31;
    const int b     = lane & 7;
    const int gbase = lane & 24;

    const long n = (long)n_start + (long)warp * 4 + (lane >> 3);
    const bool active = (n < N);

    int4   idx4 = make_int4(0, 0, 0, 0);
    float4 val4 = make_float4(0.f, 0.f, 0.f, 0.f);
    if (active) {
        const size_t base = (size_t)n * K_SYN + (size_t)b * 4;
        idx4 = *reinterpret_cast<const int4*>(indices + base);
        val4 = *reinterpret_cast<const float4*>(values + base);
    }

    const float* __restrict__ xb = x + b;
    float a0 = 0.f, a1 = 0.f, a2 = 0.f, a3 = 0.f;

    #pragma unroll
    for (int k4 = 0; k4 < 8; ++k4) {
        const int src = gbase + k4;
        const int   i0 = __shfl_sync(0xffffffffu, idx4.x, src);
        const int   i1 = __shfl_sync(0xffffffffu, idx4.y, src);
        const int   i2 = __shfl_sync(0xffffffffu, idx4.z, src);
        const int   i3 = __shfl_sync(0xffffffffu, idx4.w, src);
        const float v0 = __shfl_sync(0xffffffffu, val4.x, src);
        const float v1 = __shfl_sync(0xffffffffu, val4.y, src);
        const float v2 = __shfl_sync(0xffffffffu, val4.z, src);
        const float v3 = __shfl_sync(0xffffffffu, val4.w, src);
        a0 = fmaf(v0, __ldg(xb + (size_t)i0 * B_COL), a0);
        a1 = fmaf(v1, __ldg(xb + (size_t)i1 * B_COL), a1);
        a2 = fmaf(v2, __ldg(xb + (size_t)i2 * B_COL), a2);
        a3 = fmaf(v3, __ldg(xb + (size_t)i3 * B_COL), a3);
    }

    if (active) {
        out[(size_t)n * B_COL + b] = ((a0 + a1) + (a2 + a3)) + __ldg(bias + n);
    }
}

// ---------------------------------------------------------------------------
extern "C" void kernel_launch(void* const* d_in, const int* in_sizes, int n_in,
                              void* d_out, int out_size) {
    const float* x       = (const float*)d_in[0];
    const float* values  = (const float*)d_in[1];
    const float* bias    = (const float*)d_in[2];
    const int*   indices = (const int*)d_in[3];
    float* out = (float*)d_out;

    const int N = in_sizes[2];            // bias: one element per neuron
    const int tiles = N / TILE_N;
    const int rem   = N % TILE_N;

    // Build the gather4 tensormap host-side (driver entry via runtime API;
    // no libcuda link dependency, no statics, deterministic per call).
    bool ok = (tiles > 0);
    CUtensorMap tmap;
    if (ok) {
        typedef CUresult (*EncodeFn)(
            CUtensorMap*, CUtensorMapDataType, cuuint32_t, void*,
            const cuuint64_t*, const cuuint64_t*, const cuuint32_t*,
            const cuuint32_t*, CUtensorMapInterleave, CUtensorMapSwizzle,
            CUtensorMapL2promotion, CUtensorMapFloatOOBfill);
        void* fp = nullptr;
        cudaDriverEntryPointQueryResult qr;
        if (cudaGetDriverEntryPointByVersion("cuTensorMapEncodeTiled", &fp,
                                             12000, cudaEnableDefault, &qr)
                != cudaSuccess || fp == nullptr) {
            ok = false;
        } else {
            EncodeFn enc = (EncodeFn)fp;
            cuuint64_t dims[2]    = {(cuuint64_t)B_COL, (cuuint64_t)N};
            cuuint64_t strides[1] = {(cuuint64_t)ROW_BYTES};
            cuuint32_t box[2]     = {(cuuint32_t)B_COL, 1u};
            cuuint32_t es[2]      = {1u, 1u};
            ok = enc(&tmap, CU_TENSOR_MAP_DATA_TYPE_FLOAT32, 2, (void*)x,
                     dims, strides, box, es,
                     CU_TENSOR_MAP_INTERLEAVE_NONE,
                     CU_TENSOR_MAP_SWIZZLE_NONE,
                     CU_TENSOR_MAP_L2_PROMOTION_NONE,
                     CU_TENSOR_MAP_FLOAT_OOB_FILL_NONE) == CUDA_SUCCESS;
        }
    }
    if (ok) {
        ok = cudaFuncSetAttribute(cortical_tma_kernel,
                                  cudaFuncAttributeMaxDynamicSharedMemorySize,
                                  SMEM_TOTAL) == cudaSuccess;
    }

    if (ok) {
        cortical_tma_kernel<<<tiles, THREADS, SMEM_TOTAL>>>(
            tmap, values, bias, indices, out);
        if (rem > 0) {
            const int grid = (rem + 31) / 32;
            cortical_spmm_kernel<<<grid, 256>>>(
                x, values, bias, indices, out, tiles * TILE_N, N);
        }
    } else {
        const int grid = (N + 31) / 32;
        cortical_spmm_kernel<<<grid, 256>>>(x, values, bias, indices, out, 0, N);
    }
}